// round 5
// baseline (speedup 1.0000x reference)
#include <cuda_runtime.h>

// Problem constants
#define NN   4096
#define FIN  512
#define FOUT 256
// C (channels) = 4

// Scratch (allocation-free rule: __device__ globals)
__device__ float g_wsum[FIN * FOUT];   // 512 KB
__device__ float g_h[NN * FOUT];       // 4 MB

// ---------------------------------------------------------------------------
// packed f32x2 helpers
// ---------------------------------------------------------------------------
__device__ __forceinline__ void fma2(unsigned long long& d,
                                     unsigned long long a,
                                     unsigned long long b) {
    asm("fma.rn.f32x2 %0, %1, %2, %0;" : "+l"(d) : "l"(a), "l"(b));
}
__device__ __forceinline__ unsigned long long pk2(float x) {
    unsigned long long r;
    asm("mov.b64 %0, {%1, %1};" : "=l"(r) : "f"(x));
    return r;
}
__device__ __forceinline__ float2 unpk(unsigned long long v) {
    float2 f;
    asm("mov.b64 {%0, %1}, %2;" : "=f"(f.x), "=f"(f.y) : "l"(v));
    return f;
}

// ---------------------------------------------------------------------------
// K0: Wsum[k,j] = sum_c weight[k,j,c]   (weight is [FIN, FOUT, 4] contiguous)
// ---------------------------------------------------------------------------
__global__ void wsum_kernel(const float* __restrict__ weight) {
    int idx = blockIdx.x * blockDim.x + threadIdx.x;   // 0 .. 131071
    float4 w = reinterpret_cast<const float4*>(weight)[idx];
    g_wsum[idx] = (w.x + w.y) + (w.z + w.w);
}

// ---------------------------------------------------------------------------
// Tiled GEMM, BM=32 x BN=256, BK=32, 256 threads, register prefetch.
//   MAIN=false: g_h = x(A) @ g_wsum            (K = FIN, scalar A loads)
//   MAIN=true : out  = Asum(A) @ g_h + bias    (K = NN, A = sum4(adjs))
// Thread map: tx = tid&31 (column groups), ty = tid>>5 (row group of 4).
// Each thread: rows ty*4..+3, cols {tx*4..+3} and {128+tx*4..+3}.
// ---------------------------------------------------------------------------
constexpr int BM = 32, BN = 256, BK = 32, APAD = 36;

template <int K, bool MAIN>
__launch_bounds__(256, 1)
__global__ void gemm_kernel(const float* __restrict__ A,
                            const float* __restrict__ bias,
                            float* __restrict__ out_main) {
    __shared__ float sA[BK][APAD];   // transposed: sA[kcol][row]
    __shared__ float sB[BK][BN];

    const float* __restrict__ B = MAIN ? g_h : g_wsum;

    const int tid = threadIdx.x;
    const int tx  = tid & 31;
    const int ty  = tid >> 5;
    const int i0  = blockIdx.x * BM;

    // A-tile load map: element e = tid + i*256 -> row = e>>5, kcol = e&31
    const int a_kcol = tid & 31;
    const int a_row0 = tid >> 5;
    // B-tile load map: float4 e4 = tid + i*256 -> krow = e4>>6, col4 = e4&63
    const int b_col4  = tid & 63;
    const int b_krow0 = tid >> 6;

    unsigned long long acc[4][4];
#pragma unroll
    for (int r = 0; r < 4; r++)
#pragma unroll
        for (int p = 0; p < 4; p++) acc[r][p] = 0ULL;

    float  a_reg[4];
    float4 b_reg[8];

    auto load_tiles = [&](int kt) {
#pragma unroll
        for (int i = 0; i < 4; i++) {
            int row = a_row0 + i * 8;
            if (MAIN) {
                const float4 v = *reinterpret_cast<const float4*>(
                    A + ((size_t)(i0 + row) * K + kt + a_kcol) * 4);
                a_reg[i] = (v.x + v.y) + (v.z + v.w);
            } else {
                a_reg[i] = A[(size_t)(i0 + row) * K + kt + a_kcol];
            }
        }
#pragma unroll
        for (int i = 0; i < 8; i++) {
            int krow = b_krow0 + i * 4;
            b_reg[i] = *reinterpret_cast<const float4*>(
                B + (size_t)(kt + krow) * BN + b_col4 * 4);
        }
    };
    auto store_tiles = [&]() {
#pragma unroll
        for (int i = 0; i < 4; i++) sA[a_kcol][a_row0 + i * 8] = a_reg[i];
#pragma unroll
        for (int i = 0; i < 8; i++)
            *reinterpret_cast<float4*>(&sB[b_krow0 + i * 4][b_col4 * 4]) = b_reg[i];
    };

    load_tiles(0);
    store_tiles();
    __syncthreads();

    for (int kt = 0; kt < K; kt += BK) {
        const bool has_next = (kt + BK) < K;
        if (has_next) load_tiles(kt + BK);

#pragma unroll
        for (int kk = 0; kk < BK; kk++) {
            const float4 av = *reinterpret_cast<const float4*>(&sA[kk][ty * 4]);
            const ulonglong2 bA =
                *reinterpret_cast<const ulonglong2*>(&sB[kk][tx * 4]);
            const ulonglong2 bB =
                *reinterpret_cast<const ulonglong2*>(&sB[kk][128 + tx * 4]);
            unsigned long long a0 = pk2(av.x), a1 = pk2(av.y),
                               a2 = pk2(av.z), a3 = pk2(av.w);
            fma2(acc[0][0], a0, bA.x); fma2(acc[0][1], a0, bA.y);
            fma2(acc[0][2], a0, bB.x); fma2(acc[0][3], a0, bB.y);
            fma2(acc[1][0], a1, bA.x); fma2(acc[1][1], a1, bA.y);
            fma2(acc[1][2], a1, bB.x); fma2(acc[1][3], a1, bB.y);
            fma2(acc[2][0], a2, bA.x); fma2(acc[2][1], a2, bA.y);
            fma2(acc[2][2], a2, bB.x); fma2(acc[2][3], a2, bB.y);
            fma2(acc[3][0], a3, bA.x); fma2(acc[3][1], a3, bA.y);
            fma2(acc[3][2], a3, bB.x); fma2(acc[3][3], a3, bB.y);
        }

        if (has_next) {
            __syncthreads();
            store_tiles();
            __syncthreads();
        }
    }

    // Epilogue
#pragma unroll
    for (int r = 0; r < 4; r++) {
        const int gi = i0 + ty * 4 + r;
        if (MAIN) {
            // out[i, j, c] = acc + bias[i, j, c], layout [N, FOUT, 4]
#pragma unroll
            for (int g = 0; g < 2; g++) {
#pragma unroll
                for (int p = 0; p < 2; p++) {
                    float2 v = unpk(acc[r][g * 2 + p]);
                    float vals[2] = {v.x, v.y};
#pragma unroll
                    for (int q = 0; q < 2; q++) {
                        int j = g * 128 + tx * 4 + p * 2 + q;
                        size_t o = ((size_t)gi * FOUT + j) * 4;
                        float4 bi = *reinterpret_cast<const float4*>(bias + o);
                        float  vv = vals[q];
                        float4 ov = make_float4(vv + bi.x, vv + bi.y,
                                                vv + bi.z, vv + bi.w);
                        *reinterpret_cast<float4*>(out_main + o) = ov;
                    }
                }
            }
        } else {
            // g_h[i, j], layout [N, FOUT]
#pragma unroll
            for (int g = 0; g < 2; g++) {
                float2 v0 = unpk(acc[r][g * 2 + 0]);
                float2 v1 = unpk(acc[r][g * 2 + 1]);
                *reinterpret_cast<float4*>(
                    &g_h[(size_t)gi * FOUT + g * 128 + tx * 4]) =
                    make_float4(v0.x, v0.y, v1.x, v1.y);
            }
        }
    }
}

// ---------------------------------------------------------------------------
// launch: inputs are x[4096,512], adjs[4096,4096,4], weight[512,256,4],
// bias[4096,256,4]; output [4096,256,4] float32.
// ---------------------------------------------------------------------------
extern "C" void kernel_launch(void* const* d_in, const int* in_sizes, int n_in,
                              void* d_out, int out_size) {
    const float* x      = (const float*)d_in[0];
    const float* adjs   = (const float*)d_in[1];
    const float* weight = (const float*)d_in[2];
    const float* bias   = (const float*)d_in[3];
    float* out          = (float*)d_out;

    // K0: Wsum = sum_c weight
    wsum_kernel<<<(FIN * FOUT) / 256, 256>>>(weight);
    // K1: h = x @ Wsum
    gemm_kernel<FIN, false><<<NN / BM, 256>>>(x, nullptr, nullptr);
    // K2: out = (sum_c adjs) @ h + bias
    gemm_kernel<NN, true><<<NN / BM, 256>>>(adjs, bias, out);
}

// round 8
// speedup vs baseline: 1.8642x; 1.8642x over previous
#include <cuda_runtime.h>
#include <cuda_bf16.h>
#include <cstdint>

// Problem constants
#define NN   4096
#define FIN  512
#define FOUT 256
// C (channels) = 4

// ---------------------------------------------------------------------------
// Scratch (allocation-free rule: __device__ globals)
// ---------------------------------------------------------------------------
__device__ float g_wsum[FIN * FOUT];                 // 512 KB
__device__ float g_h[NN * FOUT];                     // 4 MB
__device__ __nv_bfloat16 g_hT_hi[FOUT * NN];         // 2 MB  (h^T, bf16 hi)
__device__ __nv_bfloat16 g_hT_lo[FOUT * NN];         // 2 MB  (h^T, bf16 lo)
__device__ __nv_bfloat16 g_A_hi[(size_t)NN * NN];    // 32 MB (Asum, bf16 hi)
__device__ __nv_bfloat16 g_A_lo[(size_t)NN * NN];    // 32 MB (Asum, bf16 lo)
__device__ float g_part[4ull * NN * FOUT];           // 16 MB (split-K partials)

// ---------------------------------------------------------------------------
// PTX helpers (sm_80-era instructions only — no 'a'-gated features; the
// harness emits PTX for plain sm_103 where tcgen05/TMA-tensor are rejected)
// ---------------------------------------------------------------------------
__device__ __forceinline__ uint32_t smem_u32(const void* p) {
    uint32_t a;
    asm("{ .reg .u64 t; cvta.to.shared.u64 t, %1; cvt.u32.u64 %0, t; }"
        : "=r"(a) : "l"(p));
    return a;
}
__device__ __forceinline__ void cp16(uint32_t sdst, const void* gsrc) {
    asm volatile("cp.async.cg.shared.global [%0], [%1], 16;"
                 :: "r"(sdst), "l"(gsrc) : "memory");
}
__device__ __forceinline__ void cp_commit() {
    asm volatile("cp.async.commit_group;" ::: "memory");
}
template <int N>
__device__ __forceinline__ void cp_wait() {
    asm volatile("cp.async.wait_group %0;" :: "n"(N) : "memory");
}
__device__ __forceinline__ void ldmx4(uint32_t& r0, uint32_t& r1,
                                      uint32_t& r2, uint32_t& r3, uint32_t a) {
    asm volatile("ldmatrix.sync.aligned.m8n8.x4.shared.b16 {%0,%1,%2,%3}, [%4];"
                 : "=r"(r0), "=r"(r1), "=r"(r2), "=r"(r3) : "r"(a));
}
__device__ __forceinline__ void hmma(float* d, const uint32_t* a,
                                     const uint32_t* b) {
    asm volatile(
        "mma.sync.aligned.m16n8k16.row.col.f32.bf16.bf16.f32 "
        "{%0,%1,%2,%3}, {%4,%5,%6,%7}, {%8,%9}, {%0,%1,%2,%3};"
        : "+f"(d[0]), "+f"(d[1]), "+f"(d[2]), "+f"(d[3])
        : "r"(a[0]), "r"(a[1]), "r"(a[2]), "r"(a[3]), "r"(b[0]), "r"(b[1]));
}

// packed f32x2 helpers (scalar K1 kernel)
__device__ __forceinline__ void fma2(unsigned long long& d,
                                     unsigned long long a,
                                     unsigned long long b) {
    asm("fma.rn.f32x2 %0, %1, %2, %0;" : "+l"(d) : "l"(a), "l"(b));
}
__device__ __forceinline__ unsigned long long pk2(float x) {
    unsigned long long r;
    asm("mov.b64 %0, {%1, %1};" : "=l"(r) : "f"(x));
    return r;
}
__device__ __forceinline__ float2 unpk(unsigned long long v) {
    float2 f;
    asm("mov.b64 {%0, %1}, %2;" : "=f"(f.x), "=f"(f.y) : "l"(v));
    return f;
}

// ---------------------------------------------------------------------------
// K0: Wsum[k,j] = sum_c weight[k,j,c]
// ---------------------------------------------------------------------------
__global__ void wsum_kernel(const float* __restrict__ weight) {
    int idx = blockIdx.x * blockDim.x + threadIdx.x;
    float4 w = reinterpret_cast<const float4*>(weight)[idx];
    g_wsum[idx] = (w.x + w.y) + (w.z + w.w);
}

// ---------------------------------------------------------------------------
// K1: g_h = x @ g_wsum   (scalar f32x2 GEMM, BM=32 x BN=256, BK=32)
// ---------------------------------------------------------------------------
constexpr int BM = 32, BN = 256, BK = 32, APAD = 36;

__launch_bounds__(256, 1)
__global__ void gemm_h(const float* __restrict__ A) {
    __shared__ float sA[BK][APAD];
    __shared__ float sB[BK][BN];
    const float* __restrict__ B = g_wsum;
    constexpr int K = FIN;

    const int tid = threadIdx.x;
    const int tx  = tid & 31;
    const int ty  = tid >> 5;
    const int i0  = blockIdx.x * BM;
    const int a_kcol = tid & 31;
    const int a_row0 = tid >> 5;
    const int b_col4  = tid & 63;
    const int b_krow0 = tid >> 6;

    unsigned long long acc[4][4];
#pragma unroll
    for (int r = 0; r < 4; r++)
#pragma unroll
        for (int p = 0; p < 4; p++) acc[r][p] = 0ULL;

    float  a_reg[4];
    float4 b_reg[8];

    auto load_tiles = [&](int kt) {
#pragma unroll
        for (int i = 0; i < 4; i++) {
            int row = a_row0 + i * 8;
            a_reg[i] = A[(size_t)(i0 + row) * K + kt + a_kcol];
        }
#pragma unroll
        for (int i = 0; i < 8; i++) {
            int krow = b_krow0 + i * 4;
            b_reg[i] = *reinterpret_cast<const float4*>(
                B + (size_t)(kt + krow) * BN + b_col4 * 4);
        }
    };
    auto store_tiles = [&]() {
#pragma unroll
        for (int i = 0; i < 4; i++) sA[a_kcol][a_row0 + i * 8] = a_reg[i];
#pragma unroll
        for (int i = 0; i < 8; i++)
            *reinterpret_cast<float4*>(&sB[b_krow0 + i * 4][b_col4 * 4]) = b_reg[i];
    };

    load_tiles(0);
    store_tiles();
    __syncthreads();

    for (int kt = 0; kt < K; kt += BK) {
        const bool has_next = (kt + BK) < K;
        if (has_next) load_tiles(kt + BK);
#pragma unroll
        for (int kk = 0; kk < BK; kk++) {
            const float4 av = *reinterpret_cast<const float4*>(&sA[kk][ty * 4]);
            const ulonglong2 bA = *reinterpret_cast<const ulonglong2*>(&sB[kk][tx * 4]);
            const ulonglong2 bB = *reinterpret_cast<const ulonglong2*>(&sB[kk][128 + tx * 4]);
            unsigned long long a0 = pk2(av.x), a1 = pk2(av.y),
                               a2 = pk2(av.z), a3 = pk2(av.w);
            fma2(acc[0][0], a0, bA.x); fma2(acc[0][1], a0, bA.y);
            fma2(acc[0][2], a0, bB.x); fma2(acc[0][3], a0, bB.y);
            fma2(acc[1][0], a1, bA.x); fma2(acc[1][1], a1, bA.y);
            fma2(acc[1][2], a1, bB.x); fma2(acc[1][3], a1, bB.y);
            fma2(acc[2][0], a2, bA.x); fma2(acc[2][1], a2, bA.y);
            fma2(acc[2][2], a2, bB.x); fma2(acc[2][3], a2, bB.y);
            fma2(acc[3][0], a3, bA.x); fma2(acc[3][1], a3, bA.y);
            fma2(acc[3][2], a3, bB.x); fma2(acc[3][3], a3, bB.y);
        }
        if (has_next) {
            __syncthreads();
            store_tiles();
            __syncthreads();
        }
    }
#pragma unroll
    for (int r = 0; r < 4; r++) {
        const int gi = i0 + ty * 4 + r;
#pragma unroll
        for (int g = 0; g < 2; g++) {
            float2 v0 = unpk(acc[r][g * 2 + 0]);
            float2 v1 = unpk(acc[r][g * 2 + 1]);
            *reinterpret_cast<float4*>(&g_h[(size_t)gi * FOUT + g * 128 + tx * 4]) =
                make_float4(v0.x, v0.y, v1.x, v1.y);
        }
    }
}

// ---------------------------------------------------------------------------
// K1b: transpose + bf16-split h -> g_hT_hi/lo  [FOUT][NN]
// ---------------------------------------------------------------------------
__global__ void transpose_split() {
    __shared__ float t[32][33];
    const int i0 = blockIdx.x * 32;   // rows of g_h (N dim)
    const int j0 = blockIdx.y * 32;   // cols of g_h (FOUT dim)
    const int tx = threadIdx.x, ty = threadIdx.y;
#pragma unroll
    for (int r = 0; r < 4; r++)
        t[ty + r * 8][tx] = g_h[(size_t)(i0 + ty + r * 8) * FOUT + j0 + tx];
    __syncthreads();
#pragma unroll
    for (int r = 0; r < 4; r++) {
        int j = j0 + ty + r * 8;      // output row (FOUT)
        int i = i0 + tx;              // output col (NN)
        float v = t[tx][ty + r * 8];
        __nv_bfloat16 hi = __float2bfloat16(v);
        float rlo = v - __bfloat162float(hi);
        g_hT_hi[(size_t)j * NN + i] = hi;
        g_hT_lo[(size_t)j * NN + i] = __float2bfloat16(rlo);
    }
}

// ---------------------------------------------------------------------------
// Phase A: Asum = sum_c adjs, bf16 hi/lo split. (HBM-bound: 268 MB in, 64 out)
// ---------------------------------------------------------------------------
__global__ void asum_split(const float* __restrict__ adjs) {
    size_t t = (size_t)blockIdx.x * blockDim.x + threadIdx.x;  // 0..2^22-1
    const float4* a4 = reinterpret_cast<const float4*>(adjs);
    unsigned short hs[4], ls[4];
#pragma unroll
    for (int e = 0; e < 4; e++) {
        float4 v = a4[t * 4 + e];
        float s = (v.x + v.y) + (v.z + v.w);
        __nv_bfloat16 h = __float2bfloat16(s);
        float r = s - __bfloat162float(h);
        hs[e] = __bfloat16_as_ushort(h);
        ls[e] = __bfloat16_as_ushort(__float2bfloat16(r));
    }
    uint2 H = make_uint2((uint32_t)hs[0] | ((uint32_t)hs[1] << 16),
                         (uint32_t)hs[2] | ((uint32_t)hs[3] << 16));
    uint2 L = make_uint2((uint32_t)ls[0] | ((uint32_t)ls[1] << 16),
                         (uint32_t)ls[2] | ((uint32_t)ls[3] << 16));
    reinterpret_cast<uint2*>(g_A_hi)[t] = H;
    reinterpret_cast<uint2*>(g_A_lo)[t] = L;
}

// ---------------------------------------------------------------------------
// K2: mma.sync (HMMA.16816 bf16) GEMM, split precision (3 products), splitK=4
//   part[sk] = Asum[:, sk*1024:(sk+1)*1024] @ h[sk*1024:(sk+1)*1024, :]
// CTA tile M=128 x N=256 (full width -> Asum read exactly once), K-chunk 32,
// 2-stage cp.async, 8 warps (warp tile 32x128), 80B smem row stride
// (16*5 -> conflict-free ldmatrix bank permutation).
// ---------------------------------------------------------------------------
constexpr int KC      = 32;                       // K per chunk
constexpr int NC2     = 1024 / KC;                // 32 chunks per CTA
constexpr int SROW_B  = 80;                       // bytes per smem row (40 bf16)
constexpr int A_MAT   = 128 * SROW_B;             // 10240 B per A matrix
constexpr int B_MAT   = 256 * SROW_B;             // 20480 B per B matrix
constexpr int STAGE2  = 2 * A_MAT + 2 * B_MAT;    // 61440 B
constexpr int SMEM2   = 2 * STAGE2;               // 122880 B

__global__ __launch_bounds__(256, 1) void mma_kernel() {
    extern __shared__ char smem[];
    const uint32_t sb = smem_u32(smem);
    const int tid  = threadIdx.x;
    const int wid  = tid >> 5;
    const int lane = tid & 31;
    const int wm   = wid >> 1;        // 0..3 -> warp row block (32 rows)
    const int wn   = wid & 1;         // 0..1 -> warp col block (128 cols)
    const int m0   = blockIdx.x * 128;
    const int sk   = blockIdx.y;
    const int k0   = sk * 1024;

    float acc[2][16][4];
#pragma unroll
    for (int mi = 0; mi < 2; mi++)
#pragma unroll
        for (int ni = 0; ni < 16; ni++)
#pragma unroll
            for (int q = 0; q < 4; q++) acc[mi][ni][q] = 0.0f;

    // cp.async tile loader: A rows 128 x 64B, B rows 256 x 64B, hi+lo each.
    auto load_chunk = [&](int c) {
        const uint32_t stage = sb + (uint32_t)(c & 1) * STAGE2;
        const int ke = k0 + c * KC;
#pragma unroll
        for (int i = 0; i < 2; i++) {
            int e = tid + i * 256;
            int row = e >> 2, c16 = e & 3;
            uint32_t so = (uint32_t)(row * SROW_B + c16 * 16);
            size_t g = (size_t)(m0 + row) * NN + ke + c16 * 8;
            cp16(stage + so,         g_A_hi + g);
            cp16(stage + A_MAT + so, g_A_lo + g);
        }
#pragma unroll
        for (int i = 0; i < 4; i++) {
            int e = tid + i * 256;
            int row = e >> 2, c16 = e & 3;
            uint32_t so = (uint32_t)(row * SROW_B + c16 * 16);
            size_t g = (size_t)row * NN + ke + c16 * 8;
            cp16(stage + 2 * A_MAT + so,         g_hT_hi + g);
            cp16(stage + 2 * A_MAT + B_MAT + so, g_hT_lo + g);
        }
        cp_commit();
    };

    // Per-lane ldmatrix base offsets (within a stage).
    // A (x4 over one 16x16 tile): row = wm*32 + mi*16 + (lane&15), khalf = lane>>4
    const uint32_t a_lane_off =
        (uint32_t)((wm * 32 + (lane & 15)) * SROW_B + ((lane >> 4) << 3) * 2);
    // B (x4 over two n8 tiles): n = wn*128 + ((lane>>4)<<3) + (lane&7),
    //                           khalf = (lane>>3)&1
    const uint32_t b_lane_off =
        (uint32_t)((wn * 128 + ((lane >> 4) << 3) + (lane & 7)) * SROW_B +
                   (((lane >> 3) & 1) << 3) * 2);

    load_chunk(0);
    load_chunk(1);

    for (int c = 0; c < NC2; c++) {
        if (c == NC2 - 1) cp_wait<0>(); else cp_wait<1>();
        __syncthreads();

        const uint32_t stage = sb + (uint32_t)(c & 1) * STAGE2;
        const uint32_t aH = stage + a_lane_off;
        const uint32_t aL = stage + A_MAT + a_lane_off;
        const uint32_t bH = stage + 2 * A_MAT + b_lane_off;
        const uint32_t bL = stage + 2 * A_MAT + B_MAT + b_lane_off;

#pragma unroll
        for (int ks = 0; ks < 2; ks++) {
            const uint32_t kb = (uint32_t)(ks * 16 * 2);  // 16 bf16 = 32B

            uint32_t ah[2][4], al[2][4], bb[16][2];
#pragma unroll
            for (int mi = 0; mi < 2; mi++)
                ldmx4(ah[mi][0], ah[mi][1], ah[mi][2], ah[mi][3],
                      aH + kb + (uint32_t)(mi * 16 * SROW_B));
#pragma unroll
            for (int mi = 0; mi < 2; mi++)
                ldmx4(al[mi][0], al[mi][1], al[mi][2], al[mi][3],
                      aL + kb + (uint32_t)(mi * 16 * SROW_B));
#pragma unroll
            for (int nb = 0; nb < 8; nb++)
                ldmx4(bb[2 * nb][0], bb[2 * nb][1],
                      bb[2 * nb + 1][0], bb[2 * nb + 1][1],
                      bH + kb + (uint32_t)(nb * 16 * SROW_B));
            // P1: Ahi * Bhi,  P2: Alo * Bhi
#pragma unroll
            for (int mi = 0; mi < 2; mi++)
#pragma unroll
                for (int ni = 0; ni < 16; ni++)
                    hmma(acc[mi][ni], ah[mi], bb[ni]);
#pragma unroll
            for (int mi = 0; mi < 2; mi++)
#pragma unroll
                for (int ni = 0; ni < 16; ni++)
                    hmma(acc[mi][ni], al[mi], bb[ni]);
            // P3: Ahi * Blo  (reuse bb registers)
#pragma unroll
            for (int nb = 0; nb < 8; nb++)
                ldmx4(bb[2 * nb][0], bb[2 * nb][1],
                      bb[2 * nb + 1][0], bb[2 * nb + 1][1],
                      bL + kb + (uint32_t)(nb * 16 * SROW_B));
#pragma unroll
            for (int mi = 0; mi < 2; mi++)
#pragma unroll
                for (int ni = 0; ni < 16; ni++)
                    hmma(acc[mi][ni], ah[mi], bb[ni]);
        }

        __syncthreads();
        if (c + 2 < NC2) load_chunk(c + 2);
    }

    // Epilogue: fp32 partials
    const int r_base = m0 + wm * 32 + (lane >> 2);
    const int c_base = wn * 128 + (lane & 3) * 2;
#pragma unroll
    for (int mi = 0; mi < 2; mi++)
#pragma unroll
        for (int h = 0; h < 2; h++) {
            const int row = r_base + mi * 16 + h * 8;
            float* dst = g_part + ((size_t)sk * NN + row) * FOUT + c_base;
#pragma unroll
            for (int ni = 0; ni < 16; ni++)
                *reinterpret_cast<float2*>(dst + ni * 8) =
                    make_float2(acc[mi][ni][2 * h], acc[mi][ni][2 * h + 1]);
        }
}

// ---------------------------------------------------------------------------
// Reduce: out[i,j,:] = sum_sk part[sk,i,j] + bias[i,j,:]
// ---------------------------------------------------------------------------
__global__ void reduce_kernel(const float* __restrict__ bias,
                              float* __restrict__ out) {
    const int t = blockIdx.x * blockDim.x + threadIdx.x;   // (i*256 + j)
    constexpr size_t P = (size_t)NN * FOUT;
    float s = (g_part[t] + g_part[t + P]) + (g_part[t + 2 * P] + g_part[t + 3 * P]);
    float4 b = reinterpret_cast<const float4*>(bias)[t];
    reinterpret_cast<float4*>(out)[t] =
        make_float4(s + b.x, s + b.y, s + b.z, s + b.w);
}

// ---------------------------------------------------------------------------
// launch
// ---------------------------------------------------------------------------
extern "C" void kernel_launch(void* const* d_in, const int* in_sizes, int n_in,
                              void* d_out, int out_size) {
    const float* x      = (const float*)d_in[0];
    const float* adjs   = (const float*)d_in[1];
    const float* weight = (const float*)d_in[2];
    const float* bias   = (const float*)d_in[3];
    float* out          = (float*)d_out;

    cudaFuncSetAttribute(mma_kernel,
                         cudaFuncAttributeMaxDynamicSharedMemorySize, SMEM2);

    // Phase A: Asum = sum_c adjs -> bf16 hi/lo (HBM-bound)
    asum_split<<<16384, 256>>>(adjs);
    // Wsum, h = x @ Wsum, transpose+split h
    wsum_kernel<<<(FIN * FOUT) / 256, 256>>>(weight);
    gemm_h<<<NN / BM, 256>>>(x);
    transpose_split<<<dim3(NN / 32, FOUT / 32), dim3(32, 8)>>>();
    // Main tensor-core GEMM (HMMA bf16 x3, split-K = 4)
    mma_kernel<<<dim3(NN / 128, 4), 256, SMEM2>>>();
    // Combine partials + bias
    reduce_kernel<<<(NN * FOUT) / 256, 256>>>(bias, out);
}

// round 9
// speedup vs baseline: 2.2973x; 1.2323x over previous
#include <cuda_runtime.h>
#include <cuda_fp16.h>
#include <cstdint>

// Problem constants
#define NN   4096
#define FIN  512
#define FOUT 256
// C (channels) = 4

// ---------------------------------------------------------------------------
// Scratch (allocation-free rule: __device__ globals)
// ---------------------------------------------------------------------------
__device__ __half g_xh[(size_t)NN * FIN];            // 4 MB  x hi (fp16)
__device__ __half g_xl[(size_t)NN * FIN];            // 4 MB  x lo
__device__ __half g_wT_hi[FOUT * FIN];               // 256 KB WsumT hi
__device__ __half g_wT_lo[FOUT * FIN];               // 256 KB WsumT lo
__device__ __half g_hT_hi[FOUT * NN];                // 2 MB  h^T hi
__device__ __half g_hT_lo[FOUT * NN];                // 2 MB  h^T lo
__device__ __half g_A[(size_t)NN * NN];              // 32 MB Asum (fp16, hi only)
__device__ float  g_part[4ull * NN * FOUT];          // 16 MB split-K partials

// ---------------------------------------------------------------------------
// PTX helpers (sm_80-era only; 'a'-gated features rejected by harness ptxas)
// ---------------------------------------------------------------------------
__device__ __forceinline__ uint32_t smem_u32(const void* p) {
    uint32_t a;
    asm("{ .reg .u64 t; cvta.to.shared.u64 t, %1; cvt.u32.u64 %0, t; }"
        : "=r"(a) : "l"(p));
    return a;
}
__device__ __forceinline__ void cp16(uint32_t sdst, const void* gsrc) {
    asm volatile("cp.async.cg.shared.global [%0], [%1], 16;"
                 :: "r"(sdst), "l"(gsrc) : "memory");
}
__device__ __forceinline__ void cp_commit() {
    asm volatile("cp.async.commit_group;" ::: "memory");
}
template <int N>
__device__ __forceinline__ void cp_wait() {
    asm volatile("cp.async.wait_group %0;" :: "n"(N) : "memory");
}
__device__ __forceinline__ void ldmx4(uint32_t& r0, uint32_t& r1,
                                      uint32_t& r2, uint32_t& r3, uint32_t a) {
    asm volatile("ldmatrix.sync.aligned.m8n8.x4.shared.b16 {%0,%1,%2,%3}, [%4];"
                 : "=r"(r0), "=r"(r1), "=r"(r2), "=r"(r3) : "r"(a));
}
__device__ __forceinline__ void hmma(float* d, const uint32_t* a,
                                     const uint32_t* b) {
    asm volatile(
        "mma.sync.aligned.m16n8k16.row.col.f32.f16.f16.f32 "
        "{%0,%1,%2,%3}, {%4,%5,%6,%7}, {%8,%9}, {%0,%1,%2,%3};"
        : "+f"(d[0]), "+f"(d[1]), "+f"(d[2]), "+f"(d[3])
        : "r"(a[0]), "r"(a[1]), "r"(a[2]), "r"(a[3]), "r"(b[0]), "r"(b[1]));
}

constexpr int SROW_B = 80;   // smem bytes per row: 64B data + 16B pad (bank permute)

// ---------------------------------------------------------------------------
// K0a: split x -> fp16 hi/lo
// ---------------------------------------------------------------------------
__global__ void x_split(const float* __restrict__ x) {
    size_t t = (size_t)blockIdx.x * blockDim.x + threadIdx.x;  // float4 idx
    float4 v = reinterpret_cast<const float4*>(x)[t];
    __half h[4], l[4];
    float vv[4] = {v.x, v.y, v.z, v.w};
#pragma unroll
    for (int e = 0; e < 4; e++) {
        h[e] = __float2half_rn(vv[e]);
        l[e] = __float2half_rn(vv[e] - __half2float(h[e]));
    }
    reinterpret_cast<uint2*>(g_xh)[t] = *reinterpret_cast<uint2*>(h);
    reinterpret_cast<uint2*>(g_xl)[t] = *reinterpret_cast<uint2*>(l);
}

// ---------------------------------------------------------------------------
// K0b: WsumT[j,k] = sum_c weight[k,j,c], split fp16 hi/lo (transposed store)
// ---------------------------------------------------------------------------
__global__ void wsum_split(const float* __restrict__ weight) {
    int idx = blockIdx.x * blockDim.x + threadIdx.x;  // k*FOUT + j
    int k = idx >> 8, j = idx & 255;
    float4 w = reinterpret_cast<const float4*>(weight)[idx];
    float s = (w.x + w.y) + (w.z + w.w);
    __half hi = __float2half_rn(s);
    g_wT_hi[j * FIN + k] = hi;
    g_wT_lo[j * FIN + k] = __float2half_rn(s - __half2float(hi));
}

// ---------------------------------------------------------------------------
// Phase A: Asum = sum_c adjs -> fp16 (hi only).  268 MB read, 32 MB write.
// ---------------------------------------------------------------------------
__global__ void asum_split(const float* __restrict__ adjs) {
    size_t t = (size_t)blockIdx.x * blockDim.x + threadIdx.x;
    const float4* a4 = reinterpret_cast<const float4*>(adjs);
    __half h[4];
#pragma unroll
    for (int e = 0; e < 4; e++) {
        float4 v = a4[t * 4 + e];
        h[e] = __float2half_rn((v.x + v.y) + (v.z + v.w));
    }
    reinterpret_cast<uint2*>(g_A)[t] = *reinterpret_cast<uint2*>(h);
}

// ---------------------------------------------------------------------------
// K1: h = x @ Wsum via HMMA (3 fp16 products -> h accurate to ~2^-22),
//     fused transposed hi/lo split epilogue -> g_hT_hi/lo [FOUT][NN].
// Tile M=32 x N=256, K-chunk 32, 8 warps (warp tile 16x64), grid 128.
// ---------------------------------------------------------------------------
constexpr int H_KC    = 32;
constexpr int H_NC    = FIN / H_KC;            // 16
constexpr int H_AMAT  = 32 * SROW_B;           // 2560
constexpr int H_BMAT  = 256 * SROW_B;          // 20480
constexpr int H_STAGE = 2 * H_AMAT + 2 * H_BMAT;  // 46080
constexpr int H_SMEM  = 2 * H_STAGE;           // 92160 (epilogue reuses 33 KB)

__global__ __launch_bounds__(256, 1) void gemm_h_mma() {
    extern __shared__ char smem[];
    const uint32_t sb = smem_u32(smem);
    const int tid = threadIdx.x, wid = tid >> 5, lane = tid & 31;
    const int wm = wid >> 2;          // 0..1 : 16-row block
    const int wn = wid & 3;           // 0..3 : 64-col block
    const int m0 = blockIdx.x * 32;

    float acc[8][4];
#pragma unroll
    for (int ni = 0; ni < 8; ni++)
#pragma unroll
        for (int q = 0; q < 4; q++) acc[ni][q] = 0.0f;

    auto load_chunk = [&](int c) {
        const uint32_t stage = sb + (uint32_t)(c & 1) * H_STAGE;
        const int ke = c * H_KC;
        if (tid < 128) {                      // A: 32 rows x 64B, hi+lo
            int row = tid >> 2, c16 = tid & 3;
            uint32_t so = (uint32_t)(row * SROW_B + c16 * 16);
            size_t g = (size_t)(m0 + row) * FIN + ke + c16 * 8;
            cp16(stage + so,          g_xh + g);
            cp16(stage + H_AMAT + so, g_xl + g);
        }
#pragma unroll
        for (int i = 0; i < 4; i++) {         // B: 256 rows x 64B, hi+lo
            int e = tid + i * 256;
            int row = e >> 2, c16 = e & 3;
            uint32_t so = (uint32_t)(row * SROW_B + c16 * 16);
            size_t g = (size_t)row * FIN + ke + c16 * 8;
            cp16(stage + 2 * H_AMAT + so,          g_wT_hi + g);
            cp16(stage + 2 * H_AMAT + H_BMAT + so, g_wT_lo + g);
        }
        cp_commit();
    };

    const uint32_t a_lane_off =
        (uint32_t)((wm * 16 + (lane & 15)) * SROW_B + ((lane >> 4) << 3) * 2);
    const uint32_t b_lane_off =
        (uint32_t)((wn * 64 + ((lane >> 4) << 3) + (lane & 7)) * SROW_B +
                   (((lane >> 3) & 1) << 3) * 2);

    load_chunk(0);
    load_chunk(1);

    for (int c = 0; c < H_NC; c++) {
        if (c == H_NC - 1) cp_wait<0>(); else cp_wait<1>();
        __syncthreads();
        const uint32_t stage = sb + (uint32_t)(c & 1) * H_STAGE;
        const uint32_t aH = stage + a_lane_off;
        const uint32_t aL = stage + H_AMAT + a_lane_off;
        const uint32_t bH = stage + 2 * H_AMAT + b_lane_off;
        const uint32_t bL = stage + 2 * H_AMAT + H_BMAT + b_lane_off;
#pragma unroll
        for (int ks = 0; ks < 2; ks++) {
            const uint32_t kb = (uint32_t)(ks * 32);
            uint32_t ah[4], al[4], bb[8][2];
            ldmx4(ah[0], ah[1], ah[2], ah[3], aH + kb);
            ldmx4(al[0], al[1], al[2], al[3], aL + kb);
#pragma unroll
            for (int nb = 0; nb < 4; nb++)
                ldmx4(bb[2 * nb][0], bb[2 * nb][1],
                      bb[2 * nb + 1][0], bb[2 * nb + 1][1],
                      bH + kb + (uint32_t)(nb * 16 * SROW_B));
#pragma unroll
            for (int ni = 0; ni < 8; ni++) hmma(acc[ni], ah, bb[ni]);   // xhi*Whi
#pragma unroll
            for (int ni = 0; ni < 8; ni++) hmma(acc[ni], al, bb[ni]);   // xlo*Whi
#pragma unroll
            for (int nb = 0; nb < 4; nb++)
                ldmx4(bb[2 * nb][0], bb[2 * nb][1],
                      bb[2 * nb + 1][0], bb[2 * nb + 1][1],
                      bL + kb + (uint32_t)(nb * 16 * SROW_B));
#pragma unroll
            for (int ni = 0; ni < 8; ni++) hmma(acc[ni], ah, bb[ni]);   // xhi*Wlo
        }
        __syncthreads();
        if (c + 2 < H_NC) load_chunk(c + 2);
    }

    // Epilogue: stage h tile (32 x 256 fp32) in smem, then transposed split.
    float* st = reinterpret_cast<float*>(smem);        // stride 257 (scalar)
    __syncthreads();
    {
        const int r0 = wm * 16 + (lane >> 2);
        const int c0 = wn * 64 + (lane & 3) * 2;
#pragma unroll
        for (int ni = 0; ni < 8; ni++)
#pragma unroll
            for (int h = 0; h < 2; h++) {
                st[(r0 + h * 8) * 257 + c0 + ni * 8]     = acc[ni][2 * h];
                st[(r0 + h * 8) * 257 + c0 + ni * 8 + 1] = acc[ni][2 * h + 1];
            }
    }
    __syncthreads();
    {
        const int j = tid;                 // output row (FOUT)
        __half hh[32], hl[32];
#pragma unroll
        for (int i = 0; i < 32; i++) {
            float v = st[i * 257 + j];
            hh[i] = __float2half_rn(v);
            hl[i] = __float2half_rn(v - __half2float(hh[i]));
        }
        uint4* dh = reinterpret_cast<uint4*>(g_hT_hi + (size_t)j * NN + m0);
        uint4* dl = reinterpret_cast<uint4*>(g_hT_lo + (size_t)j * NN + m0);
#pragma unroll
        for (int q = 0; q < 4; q++) {
            dh[q] = reinterpret_cast<uint4*>(hh)[q];
            dl[q] = reinterpret_cast<uint4*>(hl)[q];
        }
    }
}

// ---------------------------------------------------------------------------
// K2: main HMMA GEMM, A = Asum fp16 (hi only), B = hT fp16 hi/lo (2 products)
//   part[sk] = A[:, sk*1024:+1024] @ h[sk*1024:+1024, :]
// CTA tile 128 x 256, K-chunk 32, split-K=4 -> grid 128, 8 warps (32x128).
// ---------------------------------------------------------------------------
constexpr int KC     = 32;
constexpr int NC2    = 1024 / KC;                 // 32
constexpr int A_MAT  = 128 * SROW_B;              // 10240
constexpr int B_MAT  = 256 * SROW_B;              // 20480
constexpr int STAGE2 = A_MAT + 2 * B_MAT;         // 51200
constexpr int SMEM2  = 2 * STAGE2;                // 102400

__global__ __launch_bounds__(256, 1) void mma_kernel() {
    extern __shared__ char smem[];
    const uint32_t sb = smem_u32(smem);
    const int tid  = threadIdx.x;
    const int wid  = tid >> 5;
    const int lane = tid & 31;
    const int wm   = wid >> 1;        // 0..3 -> 32-row block
    const int wn   = wid & 1;         // 0..1 -> 128-col block
    const int m0   = blockIdx.x * 128;
    const int sk   = blockIdx.y;
    const int k0   = sk * 1024;

    float acc[2][16][4];
#pragma unroll
    for (int mi = 0; mi < 2; mi++)
#pragma unroll
        for (int ni = 0; ni < 16; ni++)
#pragma unroll
            for (int q = 0; q < 4; q++) acc[mi][ni][q] = 0.0f;

    auto load_chunk = [&](int c) {
        const uint32_t stage = sb + (uint32_t)(c & 1) * STAGE2;
        const int ke = k0 + c * KC;
#pragma unroll
        for (int i = 0; i < 2; i++) {         // A: 128 rows x 64B
            int e = tid + i * 256;
            int row = e >> 2, c16 = e & 3;
            uint32_t so = (uint32_t)(row * SROW_B + c16 * 16);
            size_t g = (size_t)(m0 + row) * NN + ke + c16 * 8;
            cp16(stage + so, g_A + g);
        }
#pragma unroll
        for (int i = 0; i < 4; i++) {         // B: 256 rows x 64B, hi+lo
            int e = tid + i * 256;
            int row = e >> 2, c16 = e & 3;
            uint32_t so = (uint32_t)(row * SROW_B + c16 * 16);
            size_t g = (size_t)row * NN + ke + c16 * 8;
            cp16(stage + A_MAT + so,         g_hT_hi + g);
            cp16(stage + A_MAT + B_MAT + so, g_hT_lo + g);
        }
        cp_commit();
    };

    const uint32_t a_lane_off =
        (uint32_t)((wm * 32 + (lane & 15)) * SROW_B + ((lane >> 4) << 3) * 2);
    const uint32_t b_lane_off =
        (uint32_t)((wn * 128 + ((lane >> 4) << 3) + (lane & 7)) * SROW_B +
                   (((lane >> 3) & 1) << 3) * 2);

    load_chunk(0);
    load_chunk(1);

    for (int c = 0; c < NC2; c++) {
        if (c == NC2 - 1) cp_wait<0>(); else cp_wait<1>();
        __syncthreads();
        const uint32_t stage = sb + (uint32_t)(c & 1) * STAGE2;
        const uint32_t aH = stage + a_lane_off;
        const uint32_t bH = stage + A_MAT + b_lane_off;
        const uint32_t bL = stage + A_MAT + B_MAT + b_lane_off;
#pragma unroll
        for (int ks = 0; ks < 2; ks++) {
            const uint32_t kb = (uint32_t)(ks * 32);
            uint32_t ah[2][4], bb[16][2];
#pragma unroll
            for (int mi = 0; mi < 2; mi++)
                ldmx4(ah[mi][0], ah[mi][1], ah[mi][2], ah[mi][3],
                      aH + kb + (uint32_t)(mi * 16 * SROW_B));
#pragma unroll
            for (int nb = 0; nb < 8; nb++)
                ldmx4(bb[2 * nb][0], bb[2 * nb][1],
                      bb[2 * nb + 1][0], bb[2 * nb + 1][1],
                      bH + kb + (uint32_t)(nb * 16 * SROW_B));
#pragma unroll
            for (int mi = 0; mi < 2; mi++)
#pragma unroll
                for (int ni = 0; ni < 16; ni++)
                    hmma(acc[mi][ni], ah[mi], bb[ni]);    // A*Bhi
#pragma unroll
            for (int nb = 0; nb < 8; nb++)
                ldmx4(bb[2 * nb][0], bb[2 * nb][1],
                      bb[2 * nb + 1][0], bb[2 * nb + 1][1],
                      bL + kb + (uint32_t)(nb * 16 * SROW_B));
#pragma unroll
            for (int mi = 0; mi < 2; mi++)
#pragma unroll
                for (int ni = 0; ni < 16; ni++)
                    hmma(acc[mi][ni], ah[mi], bb[ni]);    // A*Blo
        }
        __syncthreads();
        if (c + 2 < NC2) load_chunk(c + 2);
    }

    // Epilogue: fp32 partials
    const int r_base = m0 + wm * 32 + (lane >> 2);
    const int c_base = wn * 128 + (lane & 3) * 2;
#pragma unroll
    for (int mi = 0; mi < 2; mi++)
#pragma unroll
        for (int h = 0; h < 2; h++) {
            const int row = r_base + mi * 16 + h * 8;
            float* dst = g_part + ((size_t)sk * NN + row) * FOUT + c_base;
#pragma unroll
            for (int ni = 0; ni < 16; ni++)
                *reinterpret_cast<float2*>(dst + ni * 8) =
                    make_float2(acc[mi][ni][2 * h], acc[mi][ni][2 * h + 1]);
        }
}

// ---------------------------------------------------------------------------
// Reduce: out[i,j,:] = sum_sk part[sk,i,j] + bias[i,j,:]
// ---------------------------------------------------------------------------
__global__ void reduce_kernel(const float* __restrict__ bias,
                              float* __restrict__ out) {
    const int t = blockIdx.x * blockDim.x + threadIdx.x;   // (i*256 + j)
    constexpr size_t P = (size_t)NN * FOUT;
    float s = (g_part[t] + g_part[t + P]) + (g_part[t + 2 * P] + g_part[t + 3 * P]);
    float4 b = reinterpret_cast<const float4*>(bias)[t];
    reinterpret_cast<float4*>(out)[t] =
        make_float4(s + b.x, s + b.y, s + b.z, s + b.w);
}

// ---------------------------------------------------------------------------
// launch
// ---------------------------------------------------------------------------
extern "C" void kernel_launch(void* const* d_in, const int* in_sizes, int n_in,
                              void* d_out, int out_size) {
    const float* x      = (const float*)d_in[0];
    const float* adjs   = (const float*)d_in[1];
    const float* weight = (const float*)d_in[2];
    const float* bias   = (const float*)d_in[3];
    float* out          = (float*)d_out;

    cudaFuncSetAttribute(gemm_h_mma,
                         cudaFuncAttributeMaxDynamicSharedMemorySize, H_SMEM);
    cudaFuncSetAttribute(mma_kernel,
                         cudaFuncAttributeMaxDynamicSharedMemorySize, SMEM2);

    // Phase A: Asum -> fp16 (HBM-bound, dominant)
    asum_split<<<16384, 256>>>(adjs);
    // Splits + h GEMM (HMMA) with fused transpose/split epilogue
    x_split<<<(NN * FIN / 4) / 256, 256>>>(x);
    wsum_split<<<(FIN * FOUT) / 256, 256>>>(weight);
    gemm_h_mma<<<NN / 32, 256, H_SMEM>>>();
    // Main GEMM (fp16 HMMA x2 products, split-K = 4)
    mma_kernel<<<dim3(NN / 128, 4), 256, SMEM2>>>();
    // Combine partials + bias
    reduce_kernel<<<(NN * FOUT) / 256, 256>>>(bias, out);
}

// round 10
// speedup vs baseline: 2.5342x; 1.1031x over previous
#include <cuda_runtime.h>
#include <cuda_fp16.h>
#include <cstdint>

// Problem constants
#define NN   4096
#define FIN  512
#define FOUT 256
// C (channels) = 4

// ---------------------------------------------------------------------------
// Scratch (allocation-free rule: __device__ globals)
// ---------------------------------------------------------------------------
__device__ __half g_xh[(size_t)NN * FIN];            // 4 MB  x hi (fp16)
__device__ __half g_xl[(size_t)NN * FIN];            // 4 MB  x lo
__device__ __half g_wT_hi[FOUT * FIN];               // 256 KB WsumT hi
__device__ __half g_wT_lo[FOUT * FIN];               // 256 KB WsumT lo
__device__ __half g_hT[FOUT * NN];                   // 2 MB  h^T (fp16)
__device__ __half g_A[(size_t)NN * NN];              // 32 MB Asum (fp16)
__device__ float  g_part[2ull * NN * FOUT];          // 8 MB split-K partials

// ---------------------------------------------------------------------------
// PTX helpers (sm_80-era only; 'a'-gated features rejected by harness ptxas)
// ---------------------------------------------------------------------------
__device__ __forceinline__ uint32_t smem_u32(const void* p) {
    uint32_t a;
    asm("{ .reg .u64 t; cvta.to.shared.u64 t, %1; cvt.u32.u64 %0, t; }"
        : "=r"(a) : "l"(p));
    return a;
}
__device__ __forceinline__ void cp16(uint32_t sdst, const void* gsrc) {
    asm volatile("cp.async.cg.shared.global [%0], [%1], 16;"
                 :: "r"(sdst), "l"(gsrc) : "memory");
}
__device__ __forceinline__ void cp_commit() {
    asm volatile("cp.async.commit_group;" ::: "memory");
}
template <int N>
__device__ __forceinline__ void cp_wait() {
    asm volatile("cp.async.wait_group %0;" :: "n"(N) : "memory");
}
__device__ __forceinline__ void ldmx4(uint32_t& r0, uint32_t& r1,
                                      uint32_t& r2, uint32_t& r3, uint32_t a) {
    asm volatile("ldmatrix.sync.aligned.m8n8.x4.shared.b16 {%0,%1,%2,%3}, [%4];"
                 : "=r"(r0), "=r"(r1), "=r"(r2), "=r"(r3) : "r"(a));
}
__device__ __forceinline__ void hmma(float* d, const uint32_t* a,
                                     const uint32_t* b) {
    asm volatile(
        "mma.sync.aligned.m16n8k16.row.col.f32.f16.f16.f32 "
        "{%0,%1,%2,%3}, {%4,%5,%6,%7}, {%8,%9}, {%0,%1,%2,%3};"
        : "+f"(d[0]), "+f"(d[1]), "+f"(d[2]), "+f"(d[3])
        : "r"(a[0]), "r"(a[1]), "r"(a[2]), "r"(a[3]), "r"(b[0]), "r"(b[1]));
}

constexpr int SROW_B = 80;   // smem row stride: 64B data + 16B pad (bank permute)

// ---------------------------------------------------------------------------
// K0a: split x -> fp16 hi/lo
// ---------------------------------------------------------------------------
__global__ void x_split(const float* __restrict__ x) {
    size_t t = (size_t)blockIdx.x * blockDim.x + threadIdx.x;  // float4 idx
    float4 v = reinterpret_cast<const float4*>(x)[t];
    __half h[4], l[4];
    float vv[4] = {v.x, v.y, v.z, v.w};
#pragma unroll
    for (int e = 0; e < 4; e++) {
        h[e] = __float2half_rn(vv[e]);
        l[e] = __float2half_rn(vv[e] - __half2float(h[e]));
    }
    reinterpret_cast<uint2*>(g_xh)[t] = *reinterpret_cast<uint2*>(h);
    reinterpret_cast<uint2*>(g_xl)[t] = *reinterpret_cast<uint2*>(l);
}

// ---------------------------------------------------------------------------
// K0b: WsumT[j,k] = sum_c weight[k,j,c], split fp16 hi/lo (transposed store)
// ---------------------------------------------------------------------------
__global__ void wsum_split(const float* __restrict__ weight) {
    int idx = blockIdx.x * blockDim.x + threadIdx.x;  // k*FOUT + j
    int k = idx >> 8, j = idx & 255;
    float4 w = reinterpret_cast<const float4*>(weight)[idx];
    float s = (w.x + w.y) + (w.z + w.w);
    __half hi = __float2half_rn(s);
    g_wT_hi[j * FIN + k] = hi;
    g_wT_lo[j * FIN + k] = __float2half_rn(s - __half2float(hi));
}

// ---------------------------------------------------------------------------
// Phase A: Asum = sum_c adjs -> fp16.  268 MB read, 32 MB write (HBM-bound).
// ---------------------------------------------------------------------------
__global__ void asum_split(const float* __restrict__ adjs) {
    size_t t = (size_t)blockIdx.x * blockDim.x + threadIdx.x;
    const float4* a4 = reinterpret_cast<const float4*>(adjs);
    __half h[4];
#pragma unroll
    for (int e = 0; e < 4; e++) {
        float4 v = a4[t * 4 + e];
        h[e] = __float2half_rn((v.x + v.y) + (v.z + v.w));
    }
    reinterpret_cast<uint2*>(g_A)[t] = *reinterpret_cast<uint2*>(h);
}

// ---------------------------------------------------------------------------
// K1: h^T computed DIRECTLY (flipped layout, no transpose epilogue):
//   D[j, i] = sum_k WsumT[j,k] * x[i,k]   (3 fp16 products -> accurate h)
// A = WsumT hi/lo [FOUT, FIN], B = x hi/lo [NN, FIN], D -> g_hT fp16.
// CTA tile M=64(j) x N=256(i), K-chunk 32, grid (4, 16) = 64, 3-stage.
// ---------------------------------------------------------------------------
constexpr int HF_KC    = 32;
constexpr int HF_NC    = FIN / HF_KC;              // 16
constexpr int HF_AMAT  = 64 * SROW_B;              // 5120
constexpr int HF_BMAT  = 256 * SROW_B;             // 20480
constexpr int HF_STAGE = 2 * HF_AMAT + 2 * HF_BMAT;  // 51200
constexpr int HF_SMEM  = 3 * HF_STAGE;             // 153600

__global__ __launch_bounds__(256, 1) void gemm_h_mma() {
    extern __shared__ char smem[];
    const uint32_t sb = smem_u32(smem);
    const int tid = threadIdx.x, wid = tid >> 5, lane = tid & 31;
    const int wm = wid >> 2;          // 0..1 : 32-row (j) block
    const int wn = wid & 3;           // 0..3 : 64-col (i) block
    const int m0 = blockIdx.x * 64;   // j base
    const int n0 = blockIdx.y * 256;  // i base

    float acc[2][8][4];
#pragma unroll
    for (int mi = 0; mi < 2; mi++)
#pragma unroll
        for (int ni = 0; ni < 8; ni++)
#pragma unroll
            for (int q = 0; q < 4; q++) acc[mi][ni][q] = 0.0f;

    auto load_chunk = [&](int c) {
        const uint32_t stage = sb + (uint32_t)(c % 3) * HF_STAGE;
        const int ke = c * HF_KC;
        {                                     // A: 64 rows x 64B, hi+lo
            int row = tid >> 2, c16 = tid & 3;
            uint32_t so = (uint32_t)(row * SROW_B + c16 * 16);
            size_t g = (size_t)(m0 + row) * FIN + ke + c16 * 8;
            cp16(stage + so,           g_wT_hi + g);
            cp16(stage + HF_AMAT + so, g_wT_lo + g);
        }
#pragma unroll
        for (int i = 0; i < 4; i++) {         // B: 256 rows x 64B, hi+lo
            int e = tid + i * 256;
            int row = e >> 2, c16 = e & 3;
            uint32_t so = (uint32_t)(row * SROW_B + c16 * 16);
            size_t g = (size_t)(n0 + row) * FIN + ke + c16 * 8;
            cp16(stage + 2 * HF_AMAT + so,            g_xh + g);
            cp16(stage + 2 * HF_AMAT + HF_BMAT + so,  g_xl + g);
        }
        cp_commit();
    };

    const uint32_t a_lane_off =
        (uint32_t)((wm * 32 + (lane & 15)) * SROW_B + ((lane >> 4) << 3) * 2);
    const uint32_t b_lane_off =
        (uint32_t)((wn * 64 + ((lane >> 4) << 3) + (lane & 7)) * SROW_B +
                   (((lane >> 3) & 1) << 3) * 2);

    load_chunk(0);
    load_chunk(1);
    load_chunk(2);

    for (int c = 0; c < HF_NC; c++) {
        {   // wait for group c (min(2, HF_NC-1-c) groups may stay outstanding)
            int rem = HF_NC - 1 - c;
            if (rem >= 2) cp_wait<2>(); else if (rem == 1) cp_wait<1>();
            else cp_wait<0>();
        }
        __syncthreads();
        const uint32_t stage = sb + (uint32_t)(c % 3) * HF_STAGE;
        const uint32_t aH = stage + a_lane_off;
        const uint32_t aL = stage + HF_AMAT + a_lane_off;
        const uint32_t bH = stage + 2 * HF_AMAT + b_lane_off;
        const uint32_t bL = stage + 2 * HF_AMAT + HF_BMAT + b_lane_off;
#pragma unroll
        for (int ks = 0; ks < 2; ks++) {
            const uint32_t kb = (uint32_t)(ks * 32);
            uint32_t ah[2][4], al[2][4], bb[8][2];
#pragma unroll
            for (int mi = 0; mi < 2; mi++)
                ldmx4(ah[mi][0], ah[mi][1], ah[mi][2], ah[mi][3],
                      aH + kb + (uint32_t)(mi * 16 * SROW_B));
#pragma unroll
            for (int mi = 0; mi < 2; mi++)
                ldmx4(al[mi][0], al[mi][1], al[mi][2], al[mi][3],
                      aL + kb + (uint32_t)(mi * 16 * SROW_B));
#pragma unroll
            for (int nb = 0; nb < 4; nb++)
                ldmx4(bb[2 * nb][0], bb[2 * nb][1],
                      bb[2 * nb + 1][0], bb[2 * nb + 1][1],
                      bH + kb + (uint32_t)(nb * 16 * SROW_B));
#pragma unroll
            for (int mi = 0; mi < 2; mi++)
#pragma unroll
                for (int ni = 0; ni < 8; ni++)
                    hmma(acc[mi][ni], ah[mi], bb[ni]);   // Wh * xh
#pragma unroll
            for (int mi = 0; mi < 2; mi++)
#pragma unroll
                for (int ni = 0; ni < 8; ni++)
                    hmma(acc[mi][ni], al[mi], bb[ni]);   // Wl * xh
#pragma unroll
            for (int nb = 0; nb < 4; nb++)
                ldmx4(bb[2 * nb][0], bb[2 * nb][1],
                      bb[2 * nb + 1][0], bb[2 * nb + 1][1],
                      bL + kb + (uint32_t)(nb * 16 * SROW_B));
#pragma unroll
            for (int mi = 0; mi < 2; mi++)
#pragma unroll
                for (int ni = 0; ni < 8; ni++)
                    hmma(acc[mi][ni], ah[mi], bb[ni]);   // Wh * xl
        }
        __syncthreads();
        if (c + 3 < HF_NC) load_chunk(c + 3);
    }

    // Epilogue: write h^T fp16 directly (no transpose needed)
    const int r_base = m0 + wm * 32 + (lane >> 2);       // j
    const int c_base = n0 + wn * 64 + (lane & 3) * 2;    // i
#pragma unroll
    for (int mi = 0; mi < 2; mi++)
#pragma unroll
        for (int h = 0; h < 2; h++) {
            const int j = r_base + mi * 16 + h * 8;
#pragma unroll
            for (int ni = 0; ni < 8; ni++) {
                __half2 v = __floats2half2_rn(acc[mi][ni][2 * h],
                                              acc[mi][ni][2 * h + 1]);
                *reinterpret_cast<__half2*>(
                    g_hT + (size_t)j * NN + c_base + ni * 8) = v;
            }
        }
}

// ---------------------------------------------------------------------------
// K2: main HMMA GEMM, SINGLE product (A fp16 x h fp16).
//   part[sk][i,j] = sum_{k in half sk} Asum[i,k] * hT[j,k]
// CTA tile M=128(i) x N=128(j), K-chunk 32, split-K=2 -> grid (32,2,2)=128.
// 4-stage cp.async ring, 8 warps (warp tile 32x64).
// ---------------------------------------------------------------------------
constexpr int KC     = 32;
constexpr int NC2    = 2048 / KC;                 // 64 chunks
constexpr int A_MAT  = 128 * SROW_B;              // 10240
constexpr int B_MAT  = 128 * SROW_B;              // 10240
constexpr int STAGE2 = A_MAT + B_MAT;             // 20480
constexpr int SMEM2  = 4 * STAGE2;                // 81920

__global__ __launch_bounds__(256, 1) void mma_kernel() {
    extern __shared__ char smem[];
    const uint32_t sb = smem_u32(smem);
    const int tid  = threadIdx.x;
    const int wid  = tid >> 5;
    const int lane = tid & 31;
    const int wm   = wid >> 1;        // 0..3 -> 32-row block
    const int wn   = wid & 1;         // 0..1 -> 64-col block
    const int m0   = blockIdx.x * 128;   // i base
    const int n0   = blockIdx.y * 128;   // j base
    const int sk   = blockIdx.z;
    const int k0   = sk * 2048;

    float acc[2][8][4];
#pragma unroll
    for (int mi = 0; mi < 2; mi++)
#pragma unroll
        for (int ni = 0; ni < 8; ni++)
#pragma unroll
            for (int q = 0; q < 4; q++) acc[mi][ni][q] = 0.0f;

    auto load_chunk = [&](int c) {
        const uint32_t stage = sb + (uint32_t)(c & 3) * STAGE2;
        const int ke = k0 + c * KC;
#pragma unroll
        for (int i = 0; i < 2; i++) {         // A: 128 rows x 64B
            int e = tid + i * 256;
            int row = e >> 2, c16 = e & 3;
            uint32_t so = (uint32_t)(row * SROW_B + c16 * 16);
            size_t g = (size_t)(m0 + row) * NN + ke + c16 * 8;
            cp16(stage + so, g_A + g);
        }
#pragma unroll
        for (int i = 0; i < 2; i++) {         // B: 128 rows x 64B
            int e = tid + i * 256;
            int row = e >> 2, c16 = e & 3;
            uint32_t so = (uint32_t)(row * SROW_B + c16 * 16);
            size_t g = (size_t)(n0 + row) * NN + ke + c16 * 8;
            cp16(stage + A_MAT + so, g_hT + g);
        }
        cp_commit();
    };

    const uint32_t a_lane_off =
        (uint32_t)((wm * 32 + (lane & 15)) * SROW_B + ((lane >> 4) << 3) * 2);
    const uint32_t b_lane_off =
        (uint32_t)((wn * 64 + ((lane >> 4) << 3) + (lane & 7)) * SROW_B +
                   (((lane >> 3) & 1) << 3) * 2);

    load_chunk(0);
    load_chunk(1);
    load_chunk(2);
    load_chunk(3);

    for (int c = 0; c < NC2; c++) {
        {   // wait for group c (min(3, NC2-1-c) groups may stay outstanding)
            int rem = NC2 - 1 - c;
            if (rem >= 3) cp_wait<3>();
            else if (rem == 2) cp_wait<2>();
            else if (rem == 1) cp_wait<1>();
            else cp_wait<0>();
        }
        __syncthreads();
        const uint32_t stage = sb + (uint32_t)(c & 3) * STAGE2;
        const uint32_t aH = stage + a_lane_off;
        const uint32_t bH = stage + A_MAT + b_lane_off;
#pragma unroll
        for (int ks = 0; ks < 2; ks++) {
            const uint32_t kb = (uint32_t)(ks * 32);
            uint32_t ah[2][4], bb[8][2];
#pragma unroll
            for (int mi = 0; mi < 2; mi++)
                ldmx4(ah[mi][0], ah[mi][1], ah[mi][2], ah[mi][3],
                      aH + kb + (uint32_t)(mi * 16 * SROW_B));
#pragma unroll
            for (int nb = 0; nb < 4; nb++)
                ldmx4(bb[2 * nb][0], bb[2 * nb][1],
                      bb[2 * nb + 1][0], bb[2 * nb + 1][1],
                      bH + kb + (uint32_t)(nb * 16 * SROW_B));
#pragma unroll
            for (int mi = 0; mi < 2; mi++)
#pragma unroll
                for (int ni = 0; ni < 8; ni++)
                    hmma(acc[mi][ni], ah[mi], bb[ni]);
        }
        __syncthreads();
        if (c + 4 < NC2) load_chunk(c + 4);
    }

    // Epilogue: fp32 partials
    const int r_base = m0 + wm * 32 + (lane >> 2);
    const int c_base = n0 + wn * 64 + (lane & 3) * 2;
#pragma unroll
    for (int mi = 0; mi < 2; mi++)
#pragma unroll
        for (int h = 0; h < 2; h++) {
            const int row = r_base + mi * 16 + h * 8;
            float* dst = g_part + ((size_t)sk * NN + row) * FOUT + c_base;
#pragma unroll
            for (int ni = 0; ni < 8; ni++)
                *reinterpret_cast<float2*>(dst + ni * 8) =
                    make_float2(acc[mi][ni][2 * h], acc[mi][ni][2 * h + 1]);
        }
}

// ---------------------------------------------------------------------------
// Reduce: out[i,j,:] = part[0,i,j] + part[1,i,j] + bias[i,j,:]
// ---------------------------------------------------------------------------
__global__ void reduce_kernel(const float* __restrict__ bias,
                              float* __restrict__ out) {
    const int t = blockIdx.x * blockDim.x + threadIdx.x;   // (i*256 + j)
    constexpr size_t P = (size_t)NN * FOUT;
    float s = g_part[t] + g_part[t + P];
    float4 b = reinterpret_cast<const float4*>(bias)[t];
    reinterpret_cast<float4*>(out)[t] =
        make_float4(s + b.x, s + b.y, s + b.z, s + b.w);
}

// ---------------------------------------------------------------------------
// launch
// ---------------------------------------------------------------------------
extern "C" void kernel_launch(void* const* d_in, const int* in_sizes, int n_in,
                              void* d_out, int out_size) {
    const float* x      = (const float*)d_in[0];
    const float* adjs   = (const float*)d_in[1];
    const float* weight = (const float*)d_in[2];
    const float* bias   = (const float*)d_in[3];
    float* out          = (float*)d_out;

    cudaFuncSetAttribute(gemm_h_mma,
                         cudaFuncAttributeMaxDynamicSharedMemorySize, HF_SMEM);
    cudaFuncSetAttribute(mma_kernel,
                         cudaFuncAttributeMaxDynamicSharedMemorySize, SMEM2);

    // Phase A: Asum -> fp16 (HBM-bound, dominant)
    asum_split<<<16384, 256>>>(adjs);
    // Splits + h^T GEMM (flipped layout, no transpose)
    x_split<<<(NN * FIN / 4) / 256, 256>>>(x);
    wsum_split<<<(FIN * FOUT) / 256, 256>>>(weight);
    gemm_h_mma<<<dim3(FOUT / 64, NN / 256), 256, HF_SMEM>>>();
    // Main GEMM (fp16 HMMA, single product, split-K = 2)
    mma_kernel<<<dim3(NN / 128, FOUT / 128, 2), 256, SMEM2>>>();
    // Combine partials + bias
    reduce_kernel<<<(NN * FOUT) / 256, 256>>>(bias, out);
}

// round 11
// speedup vs baseline: 3.6074x; 1.4235x over previous
#include <cuda_runtime.h>
#include <cuda_fp16.h>
#include <cstdint>

// Problem constants
#define NN   4096
#define FIN  512
#define FOUT 256
// C (channels) = 4

// ---------------------------------------------------------------------------
// Scratch (allocation-free rule: __device__ globals)
// ---------------------------------------------------------------------------
__device__ __half g_xh[(size_t)NN * FIN];            // 4 MB  x (fp16 hi)
__device__ __half g_wT_hi[FOUT * FIN];               // 256 KB WsumT hi
__device__ __half g_wT_lo[FOUT * FIN];               // 256 KB WsumT lo
__device__ __half g_hT[FOUT * NN];                   // 2 MB  h^T (fp16)
__device__ float  g_part[4ull * NN * FOUT];          // 16 MB split-K partials

// ---------------------------------------------------------------------------
// PTX helpers (sm_80-era only; 'a'-gated features rejected by harness ptxas)
// ---------------------------------------------------------------------------
__device__ __forceinline__ uint32_t smem_u32(const void* p) {
    uint32_t a;
    asm("{ .reg .u64 t; cvta.to.shared.u64 t, %1; cvt.u32.u64 %0, t; }"
        : "=r"(a) : "l"(p));
    return a;
}
__device__ __forceinline__ void cp16(uint32_t sdst, const void* gsrc) {
    asm volatile("cp.async.cg.shared.global [%0], [%1], 16;"
                 :: "r"(sdst), "l"(gsrc) : "memory");
}
__device__ __forceinline__ void cp_commit() {
    asm volatile("cp.async.commit_group;" ::: "memory");
}
template <int N>
__device__ __forceinline__ void cp_wait() {
    asm volatile("cp.async.wait_group %0;" :: "n"(N) : "memory");
}
__device__ __forceinline__ void ldmx4(uint32_t& r0, uint32_t& r1,
                                      uint32_t& r2, uint32_t& r3, uint32_t a) {
    asm volatile("ldmatrix.sync.aligned.m8n8.x4.shared.b16 {%0,%1,%2,%3}, [%4];"
                 : "=r"(r0), "=r"(r1), "=r"(r2), "=r"(r3) : "r"(a));
}
__device__ __forceinline__ void hmma(float* d, const uint32_t* a,
                                     const uint32_t* b) {
    asm volatile(
        "mma.sync.aligned.m16n8k16.row.col.f32.f16.f16.f32 "
        "{%0,%1,%2,%3}, {%4,%5,%6,%7}, {%8,%9}, {%0,%1,%2,%3};"
        : "+f"(d[0]), "+f"(d[1]), "+f"(d[2]), "+f"(d[3])
        : "r"(a[0]), "r"(a[1]), "r"(a[2]), "r"(a[3]), "r"(b[0]), "r"(b[1]));
}

constexpr int SROW_B = 80;   // smem row stride: data + pad (bank permute)

// ---------------------------------------------------------------------------
// K0a: x -> fp16 (hi only)
// ---------------------------------------------------------------------------
__global__ void x_split(const float* __restrict__ x) {
    size_t t = (size_t)blockIdx.x * blockDim.x + threadIdx.x;  // float4 idx
    float4 v = reinterpret_cast<const float4*>(x)[t];
    __half h[4] = {__float2half_rn(v.x), __float2half_rn(v.y),
                   __float2half_rn(v.z), __float2half_rn(v.w)};
    reinterpret_cast<uint2*>(g_xh)[t] = *reinterpret_cast<uint2*>(h);
}

// ---------------------------------------------------------------------------
// K0b: WsumT[j,k] = sum_c weight[k,j,c], fp16 hi/lo (transposed store)
// ---------------------------------------------------------------------------
__global__ void wsum_split(const float* __restrict__ weight) {
    int idx = blockIdx.x * blockDim.x + threadIdx.x;  // k*FOUT + j
    int k = idx >> 8, j = idx & 255;
    float4 w = reinterpret_cast<const float4*>(weight)[idx];
    float s = (w.x + w.y) + (w.z + w.w);
    __half hi = __float2half_rn(s);
    g_wT_hi[j * FIN + k] = hi;
    g_wT_lo[j * FIN + k] = __float2half_rn(s - __half2float(hi));
}

// ---------------------------------------------------------------------------
// K1: h^T[j,i] = sum_k WsumT[j,k]*x[i,k]  (2 products: Wh*xh + Wl*xh)
// CTA tile M=64(j) x N=128(i), KC=32, grid (4, 32) = 128, 3-stage cp.async.
// ---------------------------------------------------------------------------
constexpr int HF_KC    = 32;
constexpr int HF_NC    = FIN / HF_KC;                // 16
constexpr int HF_AMAT  = 64 * SROW_B;                // 5120 (per A matrix)
constexpr int HF_BMAT  = 128 * SROW_B;               // 10240
constexpr int HF_STAGE = 2 * HF_AMAT + HF_BMAT;      // 20480
constexpr int HF_SMEM  = 3 * HF_STAGE;               // 61440

__global__ __launch_bounds__(256, 1) void gemm_h_mma() {
    extern __shared__ char smem[];
    const uint32_t sb = smem_u32(smem);
    const int tid = threadIdx.x, wid = tid >> 5, lane = tid & 31;
    const int wm = wid >> 2;          // 0..1 : 32-row (j) block
    const int wn = wid & 3;           // 0..3 : 32-col (i) block
    const int m0 = blockIdx.x * 64;   // j base
    const int n0 = blockIdx.y * 128;  // i base

    float acc[2][4][4];
#pragma unroll
    for (int mi = 0; mi < 2; mi++)
#pragma unroll
        for (int ni = 0; ni < 4; ni++)
#pragma unroll
            for (int q = 0; q < 4; q++) acc[mi][ni][q] = 0.0f;

    auto load_chunk = [&](int c) {
        const uint32_t stage = sb + (uint32_t)(c % 3) * HF_STAGE;
        const int ke = c * HF_KC;
        {                                     // A: 64 rows x 64B, hi+lo
            int row = tid >> 2, c16 = tid & 3;
            uint32_t so = (uint32_t)(row * SROW_B + c16 * 16);
            size_t g = (size_t)(m0 + row) * FIN + ke + c16 * 8;
            cp16(stage + so,           g_wT_hi + g);
            cp16(stage + HF_AMAT + so, g_wT_lo + g);
        }
#pragma unroll
        for (int i = 0; i < 2; i++) {         // B: 128 rows x 64B (xh)
            int e = tid + i * 256;
            int row = e >> 2, c16 = e & 3;
            uint32_t so = (uint32_t)(row * SROW_B + c16 * 16);
            size_t g = (size_t)(n0 + row) * FIN + ke + c16 * 8;
            cp16(stage + 2 * HF_AMAT + so, g_xh + g);
        }
        cp_commit();
    };

    const uint32_t a_lane_off =
        (uint32_t)((wm * 32 + (lane & 15)) * SROW_B + ((lane >> 4) << 3) * 2);
    const uint32_t b_lane_off =
        (uint32_t)((wn * 32 + ((lane >> 4) << 3) + (lane & 7)) * SROW_B +
                   (((lane >> 3) & 1) << 3) * 2);

    load_chunk(0);
    load_chunk(1);
    load_chunk(2);

    for (int c = 0; c < HF_NC; c++) {
        {
            int rem = HF_NC - 1 - c;
            if (rem >= 2) cp_wait<2>(); else if (rem == 1) cp_wait<1>();
            else cp_wait<0>();
        }
        __syncthreads();
        const uint32_t stage = sb + (uint32_t)(c % 3) * HF_STAGE;
        const uint32_t aH = stage + a_lane_off;
        const uint32_t aL = stage + HF_AMAT + a_lane_off;
        const uint32_t bH = stage + 2 * HF_AMAT + b_lane_off;
#pragma unroll
        for (int ks = 0; ks < 2; ks++) {
            const uint32_t kb = (uint32_t)(ks * 32);
            uint32_t ah[2][4], al[2][4], bb[4][2];
#pragma unroll
            for (int mi = 0; mi < 2; mi++)
                ldmx4(ah[mi][0], ah[mi][1], ah[mi][2], ah[mi][3],
                      aH + kb + (uint32_t)(mi * 16 * SROW_B));
#pragma unroll
            for (int mi = 0; mi < 2; mi++)
                ldmx4(al[mi][0], al[mi][1], al[mi][2], al[mi][3],
                      aL + kb + (uint32_t)(mi * 16 * SROW_B));
#pragma unroll
            for (int nb = 0; nb < 2; nb++)
                ldmx4(bb[2 * nb][0], bb[2 * nb][1],
                      bb[2 * nb + 1][0], bb[2 * nb + 1][1],
                      bH + kb + (uint32_t)(nb * 16 * SROW_B));
#pragma unroll
            for (int mi = 0; mi < 2; mi++)
#pragma unroll
                for (int ni = 0; ni < 4; ni++) {
                    hmma(acc[mi][ni], ah[mi], bb[ni]);   // Wh * xh
                    hmma(acc[mi][ni], al[mi], bb[ni]);   // Wl * xh
                }
        }
        __syncthreads();
        if (c + 3 < HF_NC) load_chunk(c + 3);
    }

    // Epilogue: write h^T fp16 directly
    const int r_base = m0 + wm * 32 + (lane >> 2);       // j
    const int c_base = n0 + wn * 32 + (lane & 3) * 2;    // i
#pragma unroll
    for (int mi = 0; mi < 2; mi++)
#pragma unroll
        for (int h = 0; h < 2; h++) {
            const int j = r_base + mi * 16 + h * 8;
#pragma unroll
            for (int ni = 0; ni < 4; ni++) {
                __half2 v = __floats2half2_rn(acc[mi][ni][2 * h],
                                              acc[mi][ni][2 * h + 1]);
                *reinterpret_cast<__half2*>(
                    g_hT + (size_t)j * NN + c_base + ni * 8) = v;
            }
        }
}

// ---------------------------------------------------------------------------
// K2 (FUSED): part[sk][i,j] = sum_k (sum_c adjs[i,k,c]) * hT[j,k]
// Reads adjs RAW (268 MB, the HBM floor), converts sum4->fp16 in registers,
// STS into the ldmatrix A tile. No Asum intermediate.
// Grid (NN/128=32, splitK=4) = 128 CTAs, 512 threads (16 warps, tile 32x64).
// CTA tile M=128(i) x N=256(j, full width -> each adjs element read ONCE),
// KC=16, A regs depth-1 pipeline, A-fp16 double buffer, B triple buffer.
// ---------------------------------------------------------------------------
constexpr int F_KC   = 16;
constexpr int F_NCH  = 1024 / F_KC;                  // 64 chunks
constexpr int F_AMAT = 128 * SROW_B;                 // 10240 (fp16 A tile)
constexpr int F_BMAT = 256 * SROW_B;                 // 20480 (fp16 B tile)
constexpr int F_SMEM = 2 * F_AMAT + 3 * F_BMAT;      // 81920

__global__ __launch_bounds__(512, 1) void mma_fused() {
    extern __shared__ char smem[];
    const uint32_t sb   = smem_u32(smem);
    const uint32_t sbB  = sb + 2 * F_AMAT;
    const int tid  = threadIdx.x;
    const int wid  = tid >> 5;
    const int lane = tid & 31;
    const int wm   = wid >> 2;          // 0..3 -> 32-row (i) block
    const int wn   = wid & 3;           // 0..3 -> 64-col (j) block
    const int m0   = blockIdx.x * 128;  // i base
    const int sk   = blockIdx.y;
    const int k0   = sk * 1024;

    // A staging map: thread covers cells (arow, akq..akq+3), 64B contiguous.
    const int arow = tid >> 2;          // 0..127
    const int akq  = (tid & 3) * 4;     // 0,4,8,12

    float acc[2][8][4];
#pragma unroll
    for (int mi = 0; mi < 2; mi++)
#pragma unroll
        for (int ni = 0; ni < 8; ni++)
#pragma unroll
            for (int q = 0; q < 4; q++) acc[mi][ni][q] = 0.0f;

    float4 stg[4];
    const float4* adjs4;   // set in launch arg below
    {
        // adjs passed via const memory-free trick: grid-constant param
    }
    // (adjs pointer comes in as kernel arg)
    // -- actual body continues in templated fashion below --
    // NOTE: this placeholder is replaced by the real parameterized kernel.
    (void)sbB; (void)arow; (void)akq; (void)stg; (void)adjs4;
    (void)acc; (void)m0; (void)sk; (void)k0; (void)wm; (void)wn; (void)lane;
}

// Real fused kernel (with adjs parameter)
__global__ __launch_bounds__(512, 1) void mma_fused_k(
    const float* __restrict__ adjs) {
    extern __shared__ char smem[];
    const uint32_t sb  = smem_u32(smem);
    const uint32_t sbB = sb + 2 * F_AMAT;
    const int tid  = threadIdx.x;
    const int wid  = tid >> 5;
    const int lane = tid & 31;
    const int wm   = wid >> 2;
    const int wn   = wid & 3;
    const int m0   = blockIdx.x * 128;
    const int sk   = blockIdx.y;
    const int k0   = sk * 1024;

    const int arow = tid >> 2;
    const int akq  = (tid & 3) * 4;

    float acc[2][8][4];
#pragma unroll
    for (int mi = 0; mi < 2; mi++)
#pragma unroll
        for (int ni = 0; ni < 8; ni++)
#pragma unroll
            for (int q = 0; q < 4; q++) acc[mi][ni][q] = 0.0f;

    float4 stg[4];

    auto ldg_stage = [&](int c) {
        const size_t base = ((size_t)(m0 + arow) * NN + k0 + c * F_KC + akq);
#pragma unroll
        for (int q = 0; q < 4; q++)
            stg[q] = reinterpret_cast<const float4*>(adjs)[base + q];
    };
    auto sts_convert = [&](int c) {
        const uint32_t abuf = sb + (uint32_t)(c & 1) * F_AMAT;
        __half h[4];
#pragma unroll
        for (int q = 0; q < 4; q++)
            h[q] = __float2half_rn((stg[q].x + stg[q].y) + (stg[q].z + stg[q].w));
        *reinterpret_cast<uint2*>(
            smem + ((c & 1) * F_AMAT + arow * SROW_B + akq * 2)) =
            *reinterpret_cast<uint2*>(h);
        (void)abuf;
    };
    auto cp_b = [&](int c) {
        if (c < F_NCH) {
            const uint32_t stage = sbB + (uint32_t)(c % 3) * F_BMAT;
            const int ke = k0 + c * F_KC;
            int row = tid >> 1, c16 = tid & 1;        // 256 rows x 2 x 16B
            uint32_t so = (uint32_t)(row * SROW_B + c16 * 16);
            cp16(stage + so, g_hT + (size_t)row * NN + ke + c16 * 8);
        }
        cp_commit();   // empty group ok past the end
    };

    const uint32_t a_lane_off =
        (uint32_t)((wm * 32 + (lane & 15)) * SROW_B + ((lane >> 4) << 3) * 2);
    const uint32_t b_lane_off =
        (uint32_t)((wn * 64 + ((lane >> 4) << 3) + (lane & 7)) * SROW_B +
                   (((lane >> 3) & 1) << 3) * 2);

    ldg_stage(0);
    cp_b(0);
    cp_b(1);

    for (int c = 0; c < F_NCH; c++) {
        sts_convert(c);                       // regs -> A fp16 buf (c&1)
        if (c + 1 < F_NCH) ldg_stage(c + 1);  // prefetch next A into regs
        cp_wait<2>();                         // B(c) complete
        __syncthreads();                      // STS visible, buffers safe
        cp_b(c + 2);                          // B into buf (c+2)%3 (safe now)

        const uint32_t aH = sb + (uint32_t)(c & 1) * F_AMAT + a_lane_off;
        const uint32_t bH = sbB + (uint32_t)(c % 3) * F_BMAT + b_lane_off;
        uint32_t ah[2][4], bb[8][2];
#pragma unroll
        for (int mi = 0; mi < 2; mi++)
            ldmx4(ah[mi][0], ah[mi][1], ah[mi][2], ah[mi][3],
                  aH + (uint32_t)(mi * 16 * SROW_B));
#pragma unroll
        for (int nb = 0; nb < 4; nb++)
            ldmx4(bb[2 * nb][0], bb[2 * nb][1],
                  bb[2 * nb + 1][0], bb[2 * nb + 1][1],
                  bH + (uint32_t)(nb * 16 * SROW_B));
#pragma unroll
        for (int mi = 0; mi < 2; mi++)
#pragma unroll
            for (int ni = 0; ni < 8; ni++)
                hmma(acc[mi][ni], ah[mi], bb[ni]);
    }

    // Epilogue: fp32 partials
    const int r_base = m0 + wm * 32 + (lane >> 2);       // i
    const int c_base = wn * 64 + (lane & 3) * 2;         // j
#pragma unroll
    for (int mi = 0; mi < 2; mi++)
#pragma unroll
        for (int h = 0; h < 2; h++) {
            const int row = r_base + mi * 16 + h * 8;
            float* dst = g_part + ((size_t)sk * NN + row) * FOUT + c_base;
#pragma unroll
            for (int ni = 0; ni < 8; ni++)
                *reinterpret_cast<float2*>(dst + ni * 8) =
                    make_float2(acc[mi][ni][2 * h], acc[mi][ni][2 * h + 1]);
        }
}

// ---------------------------------------------------------------------------
// Reduce: out[i,j,:] = sum_{sk<4} part[sk,i,j] + bias[i,j,:]
// ---------------------------------------------------------------------------
__global__ void reduce_kernel(const float* __restrict__ bias,
                              float* __restrict__ out) {
    const int t = blockIdx.x * blockDim.x + threadIdx.x;   // (i*256 + j)
    constexpr size_t P = (size_t)NN * FOUT;
    float s = (g_part[t] + g_part[t + P]) +
              (g_part[t + 2 * P] + g_part[t + 3 * P]);
    float4 b = reinterpret_cast<const float4*>(bias)[t];
    reinterpret_cast<float4*>(out)[t] =
        make_float4(s + b.x, s + b.y, s + b.z, s + b.w);
}

// ---------------------------------------------------------------------------
// launch
// ---------------------------------------------------------------------------
extern "C" void kernel_launch(void* const* d_in, const int* in_sizes, int n_in,
                              void* d_out, int out_size) {
    const float* x      = (const float*)d_in[0];
    const float* adjs   = (const float*)d_in[1];
    const float* weight = (const float*)d_in[2];
    const float* bias   = (const float*)d_in[3];
    float* out          = (float*)d_out;

    cudaFuncSetAttribute(gemm_h_mma,
                         cudaFuncAttributeMaxDynamicSharedMemorySize, HF_SMEM);
    cudaFuncSetAttribute(mma_fused_k,
                         cudaFuncAttributeMaxDynamicSharedMemorySize, F_SMEM);

    // Prep: x -> fp16, WsumT hi/lo
    x_split<<<(NN * FIN / 4) / 256, 256>>>(x);
    wsum_split<<<(FIN * FOUT) / 256, 256>>>(weight);
    // h^T = WsumT @ x^T  (HMMA, 2 products)
    gemm_h_mma<<<dim3(FOUT / 64, NN / 128), 256, HF_SMEM>>>();
    // Main fused GEMM: channel-sum + fp16 convert + HMMA, split-K=4
    mma_fused_k<<<dim3(NN / 128, 4), 512, F_SMEM>>>(adjs);
    // Combine partials + bias
    reduce_kernel<<<(NN * FOUT) / 256, 256>>>(bias, out);
}